// round 8
// baseline (speedup 1.0000x reference)
#include <cuda_runtime.h>
#include <cstdint>

// ============================================================================
// ResidualBlockWithPointsBase — mma.sync tf32 3-pass + HYBRID gather
//   y1 = conv(x, W1); BN1 fold; y1a = relu(bn1(y1));
//   y2 = conv(y1a, W2); BN2 fold; out = relu(bn2(y2) + x)
// conv: persistent CTAs over (k, 128-edge tile):
//   double-buffered gather split across engines:
//     rows  0..31  cp.async.bulk (TMA, mbarrier complete_tx)
//     rows 32..127 cp.async LDGSTS (LSU, wait_group)
//   -> in-register tf32 hi/lo -> warp mma.m16n8k8 (3xTF32, W smem pad-68,
//   column-permuted) -> red.global.add.v4.f32 scatter. 2 CTAs/SM.
// ============================================================================

#define MAXN 100352
typedef unsigned long long ull;

__device__ float g_y1[MAXN * 64];
__device__ float g_y1a[MAXN * 64];
__device__ float g_y2[MAXN * 64];
__device__ float2 g_stats[4 * 32];
__device__ float g_bn[4 * 64];

__device__ __forceinline__ float tf32_rna(float x) {
    float r;
    asm("cvt.rna.tf32.f32 %0, %1;" : "=f"(r) : "f"(x));
    return r;
}
__device__ __forceinline__ void mma_tf32(float* d, const uint32_t* a, const uint32_t* b) {
    asm volatile(
        "mma.sync.aligned.m16n8k8.row.col.f32.tf32.tf32.f32 "
        "{%0,%1,%2,%3}, {%4,%5,%6,%7}, {%8,%9}, {%0,%1,%2,%3};"
        : "+f"(d[0]), "+f"(d[1]), "+f"(d[2]), "+f"(d[3])
        : "r"(a[0]), "r"(a[1]), "r"(a[2]), "r"(a[3]), "r"(b[0]), "r"(b[1]));
}
__device__ __forceinline__ void red_add_v4(float* g, float a, float b, float c, float d) {
    asm volatile("red.global.add.v4.f32 [%0], {%1, %2, %3, %4};"
                 :: "l"(g), "f"(a), "f"(b), "f"(c), "f"(d) : "memory");
}

#define CP_ASYNC16(dst, src) \
    asm volatile("cp.async.ca.shared.global [%0], [%1], 16;" :: "r"(dst), "l"(src))
#define CP_COMMIT() asm volatile("cp.async.commit_group;" ::: "memory")
#define CP_WAIT1() asm volatile("cp.async.wait_group 1;" ::: "memory")
#define CP_WAIT0() asm volatile("cp.async.wait_group 0;" ::: "memory")

#define MBAR_WAIT(a, ph) do {                                                     \
    asm volatile("{\n\t.reg .pred P1;\n\tWL_%=:\n\t"                              \
        "mbarrier.try_wait.parity.acquire.cta.shared::cta.b64 P1, [%0], %1, 0x989680;\n\t" \
        "@P1 bra.uni WD_%=;\n\tbra.uni WL_%=;\n\tWD_%=:\n\t}"                     \
        :: "r"(a), "r"(ph) : "memory");                                           \
} while (0)

// smem float offsets
#define A_PAD 68
#define W_PAD 68
#define OFF_A0 0
#define OFF_A1 (128 * A_PAD)                 // 8704
#define OFF_WH (2 * 128 * A_PAD)             // 17408
#define OFF_WL (OFF_WH + 64 * W_PAD)         // 21760
#define OFF_MBAR (OFF_WL + 64 * W_PAD)       // 26112 (x4 = 104448, 8B aligned)
#define SMEM_FLOATS (OFF_MBAR + 4)
#define SMEM_BYTES (SMEM_FLOATS * 4)         // 104464

#define TMA_ROWS 32
#define TMA_BYTES (TMA_ROWS * 256u)          // 8192 expect_tx

// ---------------------------------------------------------------------------
__global__ __launch_bounds__(256, 2) void conv_mma_kernel(
    const float* __restrict__ xin,  // [N][64]
    const float* __restrict__ W,    // [K][64][64]
    const int* __restrict__ in_idx, const int* __restrict__ out_idx,
    float* __restrict__ yout,       // [N][64] pre-zeroed
    int nE, int K, int nblk) {
    extern __shared__ float sm[];
    float* Wh = sm + OFF_WH;  // transposed, col-permuted: Wh[colP*W_PAD + row]
    float* Wl = sm + OFF_WL;
    const uint32_t smb = (uint32_t)__cvta_generic_to_shared(sm);

    const int tid = threadIdx.x;
    const int lane = tid & 31;
    const int wid = tid >> 5;
    const int gi = lane >> 2;
    const int tq = lane & 3;
    const int EB = (wid >> 1) * 32;    // warp's edge base
    const int NBASE = (wid & 1) * 32;  // warp's cout base

    const int tilesPerK = (nE + 127) >> 7;
    const int total = K * tilesPerK;
    const int chunk = (total + nblk - 1) / nblk;
    const int it0 = blockIdx.x * chunk;
    const int it1 = min(it0 + chunk, total);
    if (it0 >= it1) return;

    if (tid == 0) {
        asm volatile("mbarrier.init.shared.b64 [%0], 1;" :: "r"(smb + 4 * OFF_MBAR) : "memory");
        asm volatile("mbarrier.init.shared.b64 [%0], 1;" :: "r"(smb + 4 * OFF_MBAR + 8) : "memory");
        asm volatile("fence.proxy.async.shared::cta;" ::: "memory");
    }
    __syncthreads();

    // gather roles:
    //   tid  0..31  : TMA bulk, row = tid
    //   tid 64..255 : LDGSTS, row = 32 + (tid-64)/2, half = (tid-64)&1 (128B each)
    const bool is_tma = (tid < TMA_ROWS);
    const bool is_lsu = (tid >= 64);
    const int grow = is_tma ? tid : (is_lsu ? (TMA_ROWS + ((tid - 64) >> 1)) : 0);
    const int ghalf = (tid - 64) & 1;

    auto load_idx = [&](int item) -> int {
        int k = item / tilesPerK;
        int e = (item - k * tilesPerK) * 128 + grow;
        return (e < nE) ? __ldg(in_idx + (size_t)k * nE + e) : 0;
    };
    auto issue = [&](int item, int src_row) {
        const uint32_t st = (uint32_t)(item & 1);
        const uint32_t mb = smb + 4 * OFF_MBAR + 8 * st;
        const uint32_t abase = smb + 4 * (st ? OFF_A1 : OFF_A0);
        if (tid == 0)
            asm volatile("mbarrier.arrive.expect_tx.shared.b64 _, [%0], %1;"
                         :: "r"(mb), "r"(TMA_BYTES) : "memory");
        if (is_tma) {
            const float* src = xin + (size_t)src_row * 64;
            uint32_t dst = abase + (uint32_t)grow * (A_PAD * 4);
            asm volatile(
                "cp.async.bulk.shared::cluster.global.mbarrier::complete_tx::bytes "
                "[%0], [%1], %2, [%3];"
                :: "r"(dst), "l"(src), "r"(256u), "r"(mb) : "memory");
        } else if (is_lsu) {
            const float* src = xin + (size_t)src_row * 64 + ghalf * 32;
            uint32_t dst = abase + 4u * ((uint32_t)grow * A_PAD + ghalf * 32);
#pragma unroll
            for (int j = 0; j < 8; j++) CP_ASYNC16(dst + j * 16, src + j * 4);
        }
        CP_COMMIT();
    };

    int cur_k = -1;
    uint32_t ph0 = 0, ph1 = 0;

    int nidx = load_idx(it0);
    issue(it0, nidx);
    nidx = (it0 + 1 < it1) ? load_idx(it0 + 1) : 0;

    for (int item = it0; item < it1; item++) {
        const int k = item / tilesPerK;
        const int tile = item - k * tilesPerK;
        const int ebase = tile * 128;
        const int st = item & 1;

        if (item + 1 < it1) {
            issue(item + 1, nidx);
            nidx = (item + 2 < it1) ? load_idx(item + 2) : 0;
            CP_WAIT1();
        } else {
            CP_WAIT0();
        }

        if (k != cur_k) {  // W restage (prev readers done via prev-iter syncthreads)
            cur_k = k;
            const float* Wk = W + (size_t)k * 4096;
            for (int i = tid; i < 4096; i += 256) {
                int row = i >> 6, colP = i & 63;
                int l16 = colP & 15;
                // inverse column permutation (for v4 scatter)
                int Lcol = (colP & ~15) + 4 * ((l16 >> 1) & 3) + 2 * ((l16 >> 3) & 1) + (l16 & 1);
                float w = __ldg(Wk + (size_t)row * 64 + Lcol);
                float hh = tf32_rna(w);
                Wh[colP * W_PAD + row] = hh;
                Wl[colP * W_PAD + row] = tf32_rna(w - hh);
            }
        }

        // wait for this tile's TMA half, then make all copies visible CTA-wide
        MBAR_WAIT(smb + 4 * OFF_MBAR + 8 * st, st ? ph1 : ph0);
        if (st) ph1 ^= 1; else ph0 ^= 1;
        __syncthreads();

        const float* Abuf = sm + (st ? OFF_A1 : OFF_A0);

        // ---- compute: 2 m-tiles x 4 n-tiles, 8 k-chunks, 3 passes ----
        float acc[2][4][4];
#pragma unroll
        for (int mt = 0; mt < 2; mt++)
#pragma unroll
            for (int nt = 0; nt < 4; nt++)
#pragma unroll
                for (int r = 0; r < 4; r++) acc[mt][nt][r] = 0.f;

#pragma unroll
        for (int kc = 0; kc < 8; kc++) {
            uint32_t ah[2][4], al[2][4];
#pragma unroll
            for (int mt = 0; mt < 2; mt++) {
                const float* p = Abuf + (EB + mt * 16 + gi) * A_PAD + kc * 8 + tq;
                float r0 = p[0], r1 = p[8 * A_PAD], r2 = p[4], r3 = p[8 * A_PAD + 4];
                float h0 = tf32_rna(r0), h1 = tf32_rna(r1);
                float h2 = tf32_rna(r2), h3 = tf32_rna(r3);
                ah[mt][0] = __float_as_uint(h0);
                ah[mt][1] = __float_as_uint(h1);
                ah[mt][2] = __float_as_uint(h2);
                ah[mt][3] = __float_as_uint(h3);
                al[mt][0] = __float_as_uint(tf32_rna(r0 - h0));
                al[mt][1] = __float_as_uint(tf32_rna(r1 - h1));
                al[mt][2] = __float_as_uint(tf32_rna(r2 - h2));
                al[mt][3] = __float_as_uint(tf32_rna(r3 - h3));
            }
#pragma unroll
            for (int nt = 0; nt < 4; nt++) {
                const int col = NBASE + nt * 8 + gi;
                const float* wp = Wh + col * W_PAD + kc * 8 + tq;
                const float* wq = Wl + col * W_PAD + kc * 8 + tq;
                uint32_t bh[2], bl[2];
                bh[0] = __float_as_uint(wp[0]);
                bh[1] = __float_as_uint(wp[4]);
                bl[0] = __float_as_uint(wq[0]);
                bl[1] = __float_as_uint(wq[4]);
#pragma unroll
                for (int mt = 0; mt < 2; mt++) {
                    mma_tf32(acc[mt][nt], ah[mt], bh);
                    mma_tf32(acc[mt][nt], al[mt], bh);
                    mma_tf32(acc[mt][nt], ah[mt], bl);
                }
            }
        }

        // ---- scatter: thread owns logical couts NBASE+16p+4tq..+3 (v4) ----
        const int* oi = out_idx + (size_t)k * nE + ebase;
#pragma unroll
        for (int mt = 0; mt < 2; mt++) {
            const int r0 = EB + mt * 16 + gi;
            const int og0 = (ebase + r0 < nE) ? __ldg(oi + r0) : -1;
            const int og1 = (ebase + r0 + 8 < nE) ? __ldg(oi + r0 + 8) : -1;
#pragma unroll
            for (int p = 0; p < 2; p++) {
                const int cbase = NBASE + 16 * p + 4 * tq;
                if (og0 >= 0)
                    red_add_v4(yout + (size_t)og0 * 64 + cbase,
                               acc[mt][2 * p][0], acc[mt][2 * p][1],
                               acc[mt][2 * p + 1][0], acc[mt][2 * p + 1][1]);
                if (og1 >= 0)
                    red_add_v4(yout + (size_t)og1 * 64 + cbase,
                               acc[mt][2 * p][2], acc[mt][2 * p][3],
                               acc[mt][2 * p + 1][2], acc[mt][2 * p + 1][3]);
            }
        }
        __syncthreads();  // all reads of stage st done -> safe to re-issue into it
    }
}

// ---------------------------------------------------------------------------
__global__ __launch_bounds__(256) void stats_kernel(const float* __restrict__ y,
                                                    float2* __restrict__ sums, int n) {
    const int lane = threadIdx.x & 31;
    const int warp = threadIdx.x >> 5;
    const int wpb = blockDim.x >> 5;

    float2 s = {0.f, 0.f}, q = {0.f, 0.f};
    for (int r = blockIdx.x * wpb + warp; r < n; r += gridDim.x * wpb) {
        float2 v = *(const float2*)(y + (size_t)r * 64 + 2 * lane);
        s.x += v.x; s.y += v.y;
        q.x = fmaf(v.x, v.x, q.x);
        q.y = fmaf(v.y, v.y, q.y);
    }
    __shared__ float2 sh_s[8][32], sh_q[8][32];
    sh_s[warp][lane] = s;
    sh_q[warp][lane] = q;
    __syncthreads();
    if (warp == 0) {
        for (int i = 1; i < wpb; i++) {
            s.x += sh_s[i][lane].x; s.y += sh_s[i][lane].y;
            q.x += sh_q[i][lane].x; q.y += sh_q[i][lane].y;
        }
        atomicAdd(&sums[lane], s);
        atomicAdd(&sums[32 + lane], q);
    }
}

__global__ void finalize_kernel(const float2* __restrict__ sums,
                                const float* __restrict__ gamma,
                                const float* __restrict__ beta,
                                float* __restrict__ bnout, float invN) {
    int l = threadIdx.x;  // 0..31 -> channels 2l, 2l+1
    float2 s = sums[l], q = sums[32 + l];
    float m0 = s.x * invN, m1 = s.y * invN;
    float v0 = fmaf(q.x, invN, -m0 * m0);
    float v1 = fmaf(q.y, invN, -m1 * m1);
    float sc0 = gamma[2 * l] * rsqrtf(v0 + 1e-5f);
    float sc1 = gamma[2 * l + 1] * rsqrtf(v1 + 1e-5f);
    bnout[2 * l] = sc0;
    bnout[2 * l + 1] = sc1;
    bnout[64 + 2 * l] = beta[2 * l] - m0 * sc0;
    bnout[64 + 2 * l + 1] = beta[2 * l + 1] - m1 * sc1;
}

// y1a = relu(bn1(y1))
__global__ __launch_bounds__(256) void apply_bn_kernel(const float4* __restrict__ y,
                                                       const float* __restrict__ bn,
                                                       float4* __restrict__ out, int n4) {
    int i = blockIdx.x * blockDim.x + threadIdx.x;
    if (i >= n4) return;
    int c4 = (i & 15) * 4;
    float4 v = y[i];
    float4 sc = *(const float4*)(bn + c4);
    float4 sh = *(const float4*)(bn + 64 + c4);
    float4 o;
    o.x = fmaxf(fmaf(v.x, sc.x, sh.x), 0.f);
    o.y = fmaxf(fmaf(v.y, sc.y, sh.y), 0.f);
    o.z = fmaxf(fmaf(v.z, sc.z, sh.z), 0.f);
    o.w = fmaxf(fmaf(v.w, sc.w, sh.w), 0.f);
    out[i] = o;
}

__global__ __launch_bounds__(256) void final_kernel(const float4* __restrict__ y2,
                                                    const float4* __restrict__ x,
                                                    const float* __restrict__ bn,
                                                    float4* __restrict__ out, int n4) {
    int i = blockIdx.x * blockDim.x + threadIdx.x;
    if (i >= n4) return;
    int c4 = (i & 15) * 4;
    float4 v = y2[i], xr = x[i];
    float4 sc = *(const float4*)(bn + c4);
    float4 sh = *(const float4*)(bn + 64 + c4);
    float4 o;
    o.x = fmaxf(fmaf(v.x, sc.x, sh.x) + xr.x, 0.f);
    o.y = fmaxf(fmaf(v.y, sc.y, sh.y) + xr.y, 0.f);
    o.z = fmaxf(fmaf(v.z, sc.z, sh.z) + xr.z, 0.f);
    o.w = fmaxf(fmaf(v.w, sc.w, sh.w) + xr.w, 0.f);
    out[i] = o;
}

// ---------------------------------------------------------------------------
extern "C" void kernel_launch(void* const* d_in, const int* in_sizes, int n_in,
                              void* d_out, int out_size) {
    const float* x      = (const float*)d_in[0];
    const float* W1     = (const float*)d_in[2];
    const float* gamma1 = (const float*)d_in[3];
    const float* beta1  = (const float*)d_in[4];
    const float* W2     = (const float*)d_in[5];
    const float* gamma2 = (const float*)d_in[6];
    const float* beta2  = (const float*)d_in[7];
    const int* in_idx   = (const int*)d_in[8];
    const int* out_idx  = (const int*)d_in[9];

    const int N = in_sizes[0] / 64;
    const int K = in_sizes[2] / (64 * 64);

    float *y1, *y1a, *y2, *bn;
    float2* stats;
    cudaGetSymbolAddress((void**)&y1, g_y1);
    cudaGetSymbolAddress((void**)&y1a, g_y1a);
    cudaGetSymbolAddress((void**)&y2, g_y2);
    cudaGetSymbolAddress((void**)&stats, g_stats);
    cudaGetSymbolAddress((void**)&bn, g_bn);

    cudaFuncSetAttribute(conv_mma_kernel,
                         cudaFuncAttributeMaxDynamicSharedMemorySize, SMEM_BYTES);

    cudaMemsetAsync(y1, 0, (size_t)N * 64 * sizeof(float));
    cudaMemsetAsync(y2, 0, (size_t)N * 64 * sizeof(float));
    cudaMemsetAsync(stats, 0, 4 * 32 * sizeof(float2));

    const int NB = 296;  // 2 CTAs per SM
    const float invN = 1.0f / (float)N;

    // layer 1
    conv_mma_kernel<<<NB, 256, SMEM_BYTES>>>(x, W1, in_idx, out_idx, y1, N, K, NB);
    stats_kernel<<<256, 256>>>(y1, stats, N);
    finalize_kernel<<<1, 32>>>(stats, gamma1, beta1, bn, invN);
    apply_bn_kernel<<<(N * 16 + 255) / 256, 256>>>((const float4*)y1, bn, (float4*)y1a, N * 16);

    // layer 2
    conv_mma_kernel<<<NB, 256, SMEM_BYTES>>>(y1a, W2, in_idx, out_idx, y2, N, K, NB);
    stats_kernel<<<256, 256>>>(y2, stats + 64, N);
    finalize_kernel<<<1, 32>>>(stats + 64, gamma2, beta2, bn + 128, invN);

    // epilogue
    final_kernel<<<(N * 16 + 255) / 256, 256>>>((const float4*)y2, (const float4*)x,
                                                bn + 128, (float4*)d_out, N * 16);
}

// round 9
// speedup vs baseline: 1.7529x; 1.7529x over previous
#include <cuda_runtime.h>
#include <cuda_bf16.h>
#include <cstdint>

// ============================================================================
// ResidualBlockWithPointsBase — mma.sync BF16 3-pass + cp.async.bulk gather
//   y1 = conv(x, W1); BN1 fold; y1a = relu(bn1(y1));
//   y2 = conv(y1a, W2); BN2 fold; out = relu(bn2(y2) + x)
// conv: persistent CTAs over (k, 128-edge tile):
//   double-buffered row gather via cp.async.bulk (256B/row, mbarrier)
//   -> in-register bf16 hi/lo split -> warp mma.m16n8k16 (3-term:
//   Ah*Bh + Al*Bh + Ah*Bl), W pre-split bf16x2 in smem (pad-36) ->
//   red.global.add.v4.f32 scatter (column-permuted). 2 CTAs/SM.
// ============================================================================

#define MAXN 100352
typedef unsigned long long ull;

__device__ float g_y1[MAXN * 64];
__device__ float g_y1a[MAXN * 64];
__device__ float g_y2[MAXN * 64];
__device__ float2 g_stats[4 * 32];
__device__ float g_bn[4 * 64];

__device__ __forceinline__ void mma_bf16(float* d, const uint32_t* a, const uint32_t* b) {
    asm volatile(
        "mma.sync.aligned.m16n8k16.row.col.f32.bf16.bf16.f32 "
        "{%0,%1,%2,%3}, {%4,%5,%6,%7}, {%8,%9}, {%0,%1,%2,%3};"
        : "+f"(d[0]), "+f"(d[1]), "+f"(d[2]), "+f"(d[3])
        : "r"(a[0]), "r"(a[1]), "r"(a[2]), "r"(a[3]), "r"(b[0]), "r"(b[1]));
}
__device__ __forceinline__ void red_add_v4(float* g, float a, float b, float c, float d) {
    asm volatile("red.global.add.v4.f32 [%0], {%1, %2, %3, %4};"
                 :: "l"(g), "f"(a), "f"(b), "f"(c), "f"(d) : "memory");
}
// split float2 (f.x = even k, f.y = odd k) into bf16x2 hi and lo (low half = f.x)
__device__ __forceinline__ void split_bf16(float2 f, uint32_t& h, uint32_t& l) {
    __nv_bfloat162 hb = __floats2bfloat162_rn(f.x, f.y);
    float hx = __bfloat162float(__low2bfloat16(hb));
    float hy = __bfloat162float(__high2bfloat16(hb));
    __nv_bfloat162 lb = __floats2bfloat162_rn(f.x - hx, f.y - hy);
    h = *reinterpret_cast<uint32_t*>(&hb);
    l = *reinterpret_cast<uint32_t*>(&lb);
}

#define MBAR_WAIT(a, ph) do {                                                     \
    asm volatile("{\n\t.reg .pred P1;\n\tWL_%=:\n\t"                              \
        "mbarrier.try_wait.parity.acquire.cta.shared::cta.b64 P1, [%0], %1, 0x989680;\n\t" \
        "@P1 bra.uni WD_%=;\n\tbra.uni WL_%=;\n\tWD_%=:\n\t}"                     \
        :: "r"(a), "r"(ph) : "memory");                                           \
} while (0)

// smem layout (floats)
#define A_PAD 72                              // row stride (floats); 288B/row
#define OFF_A0 0
#define OFF_A1 (128 * A_PAD)                  // 9216
#define OFF_W (2 * 128 * A_PAD)               // 18432 (uint32 region, 2x64x36)
#define W_PAD 36
#define OFF_MBAR (OFF_W + 2 * 64 * W_PAD)     // 23040 floats -> byte 92160
#define SMEM_FLOATS (OFF_MBAR + 4)
#define SMEM_BYTES (SMEM_FLOATS * 4)          // 92176

#define TILE_BYTES 32768u  // 128 rows x 256B payload

// ---------------------------------------------------------------------------
__global__ __launch_bounds__(256, 2) void conv_mma_kernel(
    const float* __restrict__ xin,  // [N][64]
    const float* __restrict__ W,    // [K][64][64]
    const int* __restrict__ in_idx, const int* __restrict__ out_idx,
    float* __restrict__ yout,       // [N][64] pre-zeroed
    int nE, int K, int nblk) {
    extern __shared__ float sm[];
    uint32_t* Wh2 = (uint32_t*)(sm + OFF_W);          // [col][kpair] bf16x2 hi
    uint32_t* Wl2 = Wh2 + 64 * W_PAD;                 // lo
    const uint32_t smb = (uint32_t)__cvta_generic_to_shared(sm);

    const int tid = threadIdx.x;
    const int lane = tid & 31;
    const int wid = tid >> 5;
    const int gi = lane >> 2;
    const int tq = lane & 3;
    const int EB = (wid >> 1) * 32;    // warp's edge base
    const int NBASE = (wid & 1) * 32;  // warp's cout base

    const int tilesPerK = (nE + 127) >> 7;
    const int total = K * tilesPerK;
    const int chunk = (total + nblk - 1) / nblk;
    const int it0 = blockIdx.x * chunk;
    const int it1 = min(it0 + chunk, total);
    if (it0 >= it1) return;

    if (tid == 0) {
        asm volatile("mbarrier.init.shared.b64 [%0], 1;" :: "r"(smb + 4 * OFF_MBAR) : "memory");
        asm volatile("mbarrier.init.shared.b64 [%0], 1;" :: "r"(smb + 4 * OFF_MBAR + 8) : "memory");
        asm volatile("fence.proxy.async.shared::cta;" ::: "memory");
    }
    __syncthreads();

    // gather: threads 0..127 own one row each via cp.async.bulk (256B)
    auto load_idx = [&](int item) -> int {
        int k = item / tilesPerK;
        int e = (item - k * tilesPerK) * 128 + tid;
        return (e < nE) ? __ldg(in_idx + (size_t)k * nE + e) : 0;
    };
    auto issue = [&](int item, int src_row) {
        const uint32_t st = (uint32_t)(item & 1);
        const uint32_t mb = smb + 4 * OFF_MBAR + 8 * st;
        if (tid == 0)
            asm volatile("mbarrier.arrive.expect_tx.shared.b64 _, [%0], %1;"
                         :: "r"(mb), "r"(TILE_BYTES) : "memory");
        if (tid < 128) {
            const float* src = xin + (size_t)src_row * 64;
            uint32_t dst = smb + 4 * (st ? OFF_A1 : OFF_A0) + (uint32_t)tid * (A_PAD * 4);
            asm volatile(
                "cp.async.bulk.shared::cluster.global.mbarrier::complete_tx::bytes "
                "[%0], [%1], %2, [%3];"
                :: "r"(dst), "l"(src), "r"(256u), "r"(mb) : "memory");
        }
    };

    int cur_k = -1;
    uint32_t ph0 = 0, ph1 = 0;

    int nidx = (tid < 128) ? load_idx(it0) : 0;
    issue(it0, nidx);
    nidx = (tid < 128 && it0 + 1 < it1) ? load_idx(it0 + 1) : 0;

    for (int item = it0; item < it1; item++) {
        const int k = item / tilesPerK;
        const int tile = item - k * tilesPerK;
        const int ebase = tile * 128;
        const int st = item & 1;

        if (item + 1 < it1) {
            issue(item + 1, nidx);
            nidx = (tid < 128 && item + 2 < it1) ? load_idx(item + 2) : 0;
        }

        if (k != cur_k) {  // W restage: bf16 hi/lo, k-pairs packed, col-permuted
            cur_k = k;
            const float* Wk = W + (size_t)k * 4096;
            for (int i = tid; i < 2048; i += 256) {
                int colP = i >> 5, j = i & 31;  // j = k-pair index (k = 2j, 2j+1)
                int l16 = colP & 15;
                // inverse column permutation (for v4 scatter)
                int Lcol = (colP & ~15) + 4 * ((l16 >> 1) & 3) + 2 * ((l16 >> 3) & 1) + (l16 & 1);
                float w0 = __ldg(Wk + (size_t)(2 * j) * 64 + Lcol);
                float w1 = __ldg(Wk + (size_t)(2 * j + 1) * 64 + Lcol);
                uint32_t h, l;
                split_bf16(make_float2(w0, w1), h, l);
                Wh2[colP * W_PAD + j] = h;
                Wl2[colP * W_PAD + j] = l;
            }
        }

        // wait for this tile's gather
        MBAR_WAIT(smb + 4 * OFF_MBAR + 8 * st, st ? ph1 : ph0);
        if (st) ph1 ^= 1; else ph0 ^= 1;
        __syncthreads();  // W restage + TMA data visible to all

        const float* Abuf = sm + (st ? OFF_A1 : OFF_A0);

        // ---- compute: 2 m-tiles x 4 n-tiles, 4 k-chunks (k=16), 3 terms ----
        float acc[2][4][4];
#pragma unroll
        for (int mt = 0; mt < 2; mt++)
#pragma unroll
            for (int nt = 0; nt < 4; nt++)
#pragma unroll
                for (int r = 0; r < 4; r++) acc[mt][nt][r] = 0.f;

#pragma unroll
        for (int kc = 0; kc < 4; kc++) {
            uint32_t ah[2][4], al[2][4];
#pragma unroll
            for (int mt = 0; mt < 2; mt++) {
                const float* p = Abuf + (EB + mt * 16 + gi) * A_PAD + kc * 16 + 2 * tq;
                float2 f0 = *(const float2*)(p);                 // row gi,   k 2tq,2tq+1
                float2 f1 = *(const float2*)(p + 8 * A_PAD);     // row gi+8
                float2 f2 = *(const float2*)(p + 8);             // k +8
                float2 f3 = *(const float2*)(p + 8 * A_PAD + 8);
                split_bf16(f0, ah[mt][0], al[mt][0]);
                split_bf16(f1, ah[mt][1], al[mt][1]);
                split_bf16(f2, ah[mt][2], al[mt][2]);
                split_bf16(f3, ah[mt][3], al[mt][3]);
            }
#pragma unroll
            for (int nt = 0; nt < 4; nt++) {
                const int col = NBASE + nt * 8 + gi;
                uint32_t bh[2], bl[2];
                bh[0] = Wh2[col * W_PAD + kc * 8 + tq];
                bh[1] = Wh2[col * W_PAD + kc * 8 + tq + 4];
                bl[0] = Wl2[col * W_PAD + kc * 8 + tq];
                bl[1] = Wl2[col * W_PAD + kc * 8 + tq + 4];
#pragma unroll
                for (int mt = 0; mt < 2; mt++) {
                    mma_bf16(acc[mt][nt], ah[mt], bh);
                    mma_bf16(acc[mt][nt], al[mt], bh);
                    mma_bf16(acc[mt][nt], ah[mt], bl);
                }
            }
        }

        // ---- scatter: thread owns logical couts NBASE+16p+4tq..+3 (v4) ----
        const int* oi = out_idx + (size_t)k * nE + ebase;
#pragma unroll
        for (int mt = 0; mt < 2; mt++) {
            const int r0 = EB + mt * 16 + gi;
            const int og0 = (ebase + r0 < nE) ? __ldg(oi + r0) : -1;
            const int og1 = (ebase + r0 + 8 < nE) ? __ldg(oi + r0 + 8) : -1;
#pragma unroll
            for (int p = 0; p < 2; p++) {
                const int cbase = NBASE + 16 * p + 4 * tq;
                if (og0 >= 0)
                    red_add_v4(yout + (size_t)og0 * 64 + cbase,
                               acc[mt][2 * p][0], acc[mt][2 * p][1],
                               acc[mt][2 * p + 1][0], acc[mt][2 * p + 1][1]);
                if (og1 >= 0)
                    red_add_v4(yout + (size_t)og1 * 64 + cbase,
                               acc[mt][2 * p][2], acc[mt][2 * p][3],
                               acc[mt][2 * p + 1][2], acc[mt][2 * p + 1][3]);
            }
        }
        __syncthreads();  // all reads of stage st done -> safe to re-issue into it
    }
}

// ---------------------------------------------------------------------------
__global__ __launch_bounds__(256) void stats_kernel(const float* __restrict__ y,
                                                    float2* __restrict__ sums, int n) {
    const int lane = threadIdx.x & 31;
    const int warp = threadIdx.x >> 5;
    const int wpb = blockDim.x >> 5;

    float2 s = {0.f, 0.f}, q = {0.f, 0.f};
    for (int r = blockIdx.x * wpb + warp; r < n; r += gridDim.x * wpb) {
        float2 v = *(const float2*)(y + (size_t)r * 64 + 2 * lane);
        s.x += v.x; s.y += v.y;
        q.x = fmaf(v.x, v.x, q.x);
        q.y = fmaf(v.y, v.y, q.y);
    }
    __shared__ float2 sh_s[8][32], sh_q[8][32];
    sh_s[warp][lane] = s;
    sh_q[warp][lane] = q;
    __syncthreads();
    if (warp == 0) {
        for (int i = 1; i < wpb; i++) {
            s.x += sh_s[i][lane].x; s.y += sh_s[i][lane].y;
            q.x += sh_q[i][lane].x; q.y += sh_q[i][lane].y;
        }
        atomicAdd(&sums[lane], s);
        atomicAdd(&sums[32 + lane], q);
    }
}

__global__ void finalize_kernel(const float2* __restrict__ sums,
                                const float* __restrict__ gamma,
                                const float* __restrict__ beta,
                                float* __restrict__ bnout, float invN) {
    int l = threadIdx.x;  // 0..31 -> channels 2l, 2l+1
    float2 s = sums[l], q = sums[32 + l];
    float m0 = s.x * invN, m1 = s.y * invN;
    float v0 = fmaf(q.x, invN, -m0 * m0);
    float v1 = fmaf(q.y, invN, -m1 * m1);
    float sc0 = gamma[2 * l] * rsqrtf(v0 + 1e-5f);
    float sc1 = gamma[2 * l + 1] * rsqrtf(v1 + 1e-5f);
    bnout[2 * l] = sc0;
    bnout[2 * l + 1] = sc1;
    bnout[64 + 2 * l] = beta[2 * l] - m0 * sc0;
    bnout[64 + 2 * l + 1] = beta[2 * l + 1] - m1 * sc1;
}

// y1a = relu(bn1(y1))
__global__ __launch_bounds__(256) void apply_bn_kernel(const float4* __restrict__ y,
                                                       const float* __restrict__ bn,
                                                       float4* __restrict__ out, int n4) {
    int i = blockIdx.x * blockDim.x + threadIdx.x;
    if (i >= n4) return;
    int c4 = (i & 15) * 4;
    float4 v = y[i];
    float4 sc = *(const float4*)(bn + c4);
    float4 sh = *(const float4*)(bn + 64 + c4);
    float4 o;
    o.x = fmaxf(fmaf(v.x, sc.x, sh.x), 0.f);
    o.y = fmaxf(fmaf(v.y, sc.y, sh.y), 0.f);
    o.z = fmaxf(fmaf(v.z, sc.z, sh.z), 0.f);
    o.w = fmaxf(fmaf(v.w, sc.w, sh.w), 0.f);
    out[i] = o;
}

__global__ __launch_bounds__(256) void final_kernel(const float4* __restrict__ y2,
                                                    const float4* __restrict__ x,
                                                    const float* __restrict__ bn,
                                                    float4* __restrict__ out, int n4) {
    int i = blockIdx.x * blockDim.x + threadIdx.x;
    if (i >= n4) return;
    int c4 = (i & 15) * 4;
    float4 v = y2[i], xr = x[i];
    float4 sc = *(const float4*)(bn + c4);
    float4 sh = *(const float4*)(bn + 64 + c4);
    float4 o;
    o.x = fmaxf(fmaf(v.x, sc.x, sh.x) + xr.x, 0.f);
    o.y = fmaxf(fmaf(v.y, sc.y, sh.y) + xr.y, 0.f);
    o.z = fmaxf(fmaf(v.z, sc.z, sh.z) + xr.z, 0.f);
    o.w = fmaxf(fmaf(v.w, sc.w, sh.w) + xr.w, 0.f);
    out[i] = o;
}

// ---------------------------------------------------------------------------
extern "C" void kernel_launch(void* const* d_in, const int* in_sizes, int n_in,
                              void* d_out, int out_size) {
    const float* x      = (const float*)d_in[0];
    const float* W1     = (const float*)d_in[2];
    const float* gamma1 = (const float*)d_in[3];
    const float* beta1  = (const float*)d_in[4];
    const float* W2     = (const float*)d_in[5];
    const float* gamma2 = (const float*)d_in[6];
    const float* beta2  = (const float*)d_in[7];
    const int* in_idx   = (const int*)d_in[8];
    const int* out_idx  = (const int*)d_in[9];

    const int N = in_sizes[0] / 64;
    const int K = in_sizes[2] / (64 * 64);

    float *y1, *y1a, *y2, *bn;
    float2* stats;
    cudaGetSymbolAddress((void**)&y1, g_y1);
    cudaGetSymbolAddress((void**)&y1a, g_y1a);
    cudaGetSymbolAddress((void**)&y2, g_y2);
    cudaGetSymbolAddress((void**)&stats, g_stats);
    cudaGetSymbolAddress((void**)&bn, g_bn);

    cudaFuncSetAttribute(conv_mma_kernel,
                         cudaFuncAttributeMaxDynamicSharedMemorySize, SMEM_BYTES);

    cudaMemsetAsync(y1, 0, (size_t)N * 64 * sizeof(float));
    cudaMemsetAsync(y2, 0, (size_t)N * 64 * sizeof(float));
    cudaMemsetAsync(stats, 0, 4 * 32 * sizeof(float2));

    const int NB = 296;  // 2 CTAs per SM
    const float invN = 1.0f / (float)N;

    // layer 1
    conv_mma_kernel<<<NB, 256, SMEM_BYTES>>>(x, W1, in_idx, out_idx, y1, N, K, NB);
    stats_kernel<<<256, 256>>>(y1, stats, N);
    finalize_kernel<<<1, 32>>>(stats, gamma1, beta1, bn, invN);
    apply_bn_kernel<<<(N * 16 + 255) / 256, 256>>>((const float4*)y1, bn, (float4*)y1a, N * 16);

    // layer 2
    conv_mma_kernel<<<NB, 256, SMEM_BYTES>>>(y1a, W2, in_idx, out_idx, y2, N, K, NB);
    stats_kernel<<<256, 256>>>(y2, stats + 64, N);
    finalize_kernel<<<1, 32>>>(stats + 64, gamma2, beta2, bn + 128, invN);

    // epilogue
    final_kernel<<<(N * 16 + 255) / 256, 256>>>((const float4*)y2, (const float4*)x,
                                                bn + 128, (float4*)d_out, N * 16);
}